// round 6
// baseline (speedup 1.0000x reference)
#include <cuda_runtime.h>
#include <cuda_bf16.h>

#define N_NODES 100000
#define E_EDGES 1250000
#define DIM     64
#define NL      3
#define SCAN_B  256
#define SCAN_NBLK ((N_NODES + SCAN_B - 1) / SCAN_B)   // 391

// ---- scratch (no allocations allowed) ----
__device__ float g_w[NL + 1];
__device__ int   g_cnt[N_NODES];
__device__ int   g_cur[N_NODES];
__device__ int   g_excl[N_NODES];
__device__ int   g_bsum[512];
__device__ int   g_boff[512];
__device__ int   g_rowptr[N_NODES + 1];
__device__ float2 g_ent[E_EDGES];          // .x = __int_as_float(src), .y = dis[src]
__device__ float g_dis[N_NODES];
__device__ float g_x1[N_NODES * DIM];
__device__ float g_x2[N_NODES * DIM];
__device__ float g_out[N_NODES * DIM];

// zero counters; block 0 thread 0 also does the 4-way softmax
__global__ void k_prep(const float* __restrict__ alpha) {
    int i = blockIdx.x * blockDim.x + threadIdx.x;
    if (i < N_NODES) { g_cnt[i] = 0; g_cur[i] = 0; }
    if (i == 0) {
        float m = alpha[0];
        for (int j = 1; j <= NL; j++) m = fmaxf(m, alpha[j]);
        float s = 0.f, e[NL + 1];
        for (int j = 0; j <= NL; j++) { e[j] = __expf(alpha[j] - m); s += e[j]; }
        for (int j = 0; j <= NL; j++) g_w[j] = e[j] / s;
    }
}

__global__ void k_count(const int* __restrict__ edge_index) {
    int e = blockIdx.x * blockDim.x + threadIdx.x;
    if (e < E_EDGES) atomicAdd(&g_cnt[edge_index[E_EDGES + e]], 1);
}

// per-block scan + block sums; also computes dis = rsqrt(deg) (fused)
__global__ void k_scan1() {
    __shared__ int sh[SCAN_B];
    int t = threadIdx.x, b = blockIdx.x, i = b * SCAN_B + t;
    int v = (i < N_NODES) ? g_cnt[i] : 0;
    if (i < N_NODES) g_dis[i] = (v > 0) ? rsqrtf((float)v) : 0.f;
    sh[t] = v; __syncthreads();
    #pragma unroll
    for (int off = 1; off < SCAN_B; off <<= 1) {
        int u = (t >= off) ? sh[t - off] : 0;
        __syncthreads();
        sh[t] += u;
        __syncthreads();
    }
    if (i < N_NODES) g_excl[i] = sh[t] - v;
    if (t == SCAN_B - 1) g_bsum[b] = sh[t];
}

// scan the 391 block sums in a single 512-thread block
__global__ void k_scan2() {
    __shared__ int sh[512];
    int t = threadIdx.x;
    int v = (t < SCAN_NBLK) ? g_bsum[t] : 0;
    sh[t] = v; __syncthreads();
    #pragma unroll
    for (int off = 1; off < 512; off <<= 1) {
        int u = (t >= off) ? sh[t - off] : 0;
        __syncthreads();
        sh[t] += u;
        __syncthreads();
    }
    if (t < SCAN_NBLK) g_boff[t] = sh[t] - v;
}

__global__ void k_scan3() {
    int i = blockIdx.x * blockDim.x + threadIdx.x;
    if (i < N_NODES) g_rowptr[i] = g_excl[i] + g_boff[i / SCAN_B];
    if (i == 0) g_rowptr[N_NODES] = E_EDGES;
}

// fill CSR: edge e -> slot in dst's range; one packed 8B scattered store.
// weight stored = dis[src] only; dis[dst] applied in gather epilogue.
__global__ void k_fill(const int* __restrict__ edge_index) {
    int e = blockIdx.x * blockDim.x + threadIdx.x;
    if (e < E_EDGES) {
        int s  = edge_index[e];
        int tn = edge_index[E_EDGES + e];
        int pos = g_rowptr[tn] + atomicAdd(&g_cur[tn], 1);
        g_ent[pos] = make_float2(__int_as_float(s), g_dis[s]);
    }
}

// Gather propagation: one warp per dst node, float2 per lane (256B row).
// acc = dis[dst] * sum_e dis[src_e] * x[src_e]
// Fused epilogue: xout = acc (unless LAST); out (+)= w[widx]*acc [+ w0*emb if FIRST].
template<bool FIRST, bool LAST>
__global__ void k_gather(const float* __restrict__ xin,
                         float* __restrict__ xout,
                         const float* __restrict__ emb,
                         int widx) {
    int t = threadIdx.x;
    int node = blockIdx.x * 8 + (t >> 5);
    int lane = t & 31;
    if (node >= N_NODES) return;
    int i0 = g_rowptr[node], i1 = g_rowptr[node + 1];
    float ax = 0.f, ay = 0.f;
    int i = i0;
    int lim = i1 - 3;
    for (; i < lim; i += 4) {
        float2 p0 = __ldg(&g_ent[i]);
        float2 p1 = __ldg(&g_ent[i + 1]);
        float2 p2 = __ldg(&g_ent[i + 2]);
        float2 p3 = __ldg(&g_ent[i + 3]);
        float2 v0 = *reinterpret_cast<const float2*>(xin + (size_t)__float_as_int(p0.x) * DIM + lane * 2);
        float2 v1 = *reinterpret_cast<const float2*>(xin + (size_t)__float_as_int(p1.x) * DIM + lane * 2);
        float2 v2 = *reinterpret_cast<const float2*>(xin + (size_t)__float_as_int(p2.x) * DIM + lane * 2);
        float2 v3 = *reinterpret_cast<const float2*>(xin + (size_t)__float_as_int(p3.x) * DIM + lane * 2);
        ax = fmaf(p0.y, v0.x, ax); ay = fmaf(p0.y, v0.y, ay);
        ax = fmaf(p1.y, v1.x, ax); ay = fmaf(p1.y, v1.y, ay);
        ax = fmaf(p2.y, v2.x, ax); ay = fmaf(p2.y, v2.y, ay);
        ax = fmaf(p3.y, v3.x, ax); ay = fmaf(p3.y, v3.y, ay);
    }
    for (; i < i1; i++) {
        float2 p = __ldg(&g_ent[i]);
        float2 v = *reinterpret_cast<const float2*>(xin + (size_t)__float_as_int(p.x) * DIM + lane * 2);
        ax = fmaf(p.y, v.x, ax);
        ay = fmaf(p.y, v.y, ay);
    }
    float disd = g_dis[node];
    ax *= disd; ay *= disd;
    size_t o = (size_t)node * DIM + lane * 2;
    if (!LAST)
        *reinterpret_cast<float2*>(xout + o) = make_float2(ax, ay);
    float wl = g_w[widx];
    float2* po = reinterpret_cast<float2*>(g_out + o);
    if (FIRST) {
        float2 e2 = *reinterpret_cast<const float2*>(emb + o);
        float w0 = g_w[0];
        *po = make_float2(fmaf(w0, e2.x, wl * ax), fmaf(w0, e2.y, wl * ay));
    } else {
        float2 c = *po;
        *po = make_float2(fmaf(wl, ax, c.x), fmaf(wl, ay, c.y));
    }
}

// dot: 16 lanes per edge, float4 per lane (256B coalesced row reads)
__global__ void k_dot(const int* __restrict__ eli, float* __restrict__ res) {
    int gt = blockIdx.x * blockDim.x + threadIdx.x;
    int e = gt >> 4, l = gt & 15;
    if (e >= E_EDGES) return;
    int a = __ldg(&eli[e]);
    int b = __ldg(&eli[E_EDGES + e]);
    float4 va = *reinterpret_cast<const float4*>(g_out + (size_t)a * DIM + l * 4);
    float4 vb = *reinterpret_cast<const float4*>(g_out + (size_t)b * DIM + l * 4);
    float s = va.x * vb.x + va.y * vb.y + va.z * vb.z + va.w * vb.w;
    #pragma unroll
    for (int off = 8; off > 0; off >>= 1)
        s += __shfl_xor_sync(0xffffffffu, s, off);
    if (l == 0) res[e] = s;
}

extern "C" void kernel_launch(void* const* d_in, const int* in_sizes, int n_in,
                              void* d_out, int out_size) {
    const int*   edge_index = (const int*)d_in[0];
    const int*   edge_label = (const int*)d_in[1];
    const float* emb        = (const float*)d_in[2];
    const float* alpha      = (const float*)d_in[3];
    float*       res        = (float*)d_out;

    float *x1, *x2;
    cudaGetSymbolAddress((void**)&x1, g_x1);
    cudaGetSymbolAddress((void**)&x2, g_x2);

    const int TB = 256;
    const int nblkN = (N_NODES + TB - 1) / TB;
    const int nblkE = (E_EDGES + TB - 1) / TB;
    const int nblkG = (N_NODES + 7) / 8;          // 8 nodes per 256-thread block

    // CSR build
    k_prep<<<nblkN, TB>>>(alpha);
    k_count<<<nblkE, TB>>>(edge_index);
    k_scan1<<<SCAN_NBLK, SCAN_B>>>();
    k_scan2<<<1, 512>>>();
    k_scan3<<<nblkN, TB>>>();
    k_fill<<<nblkE, TB>>>(edge_index);

    // propagation (gather, no fp atomics), out-accum fused
    k_gather<true,  false><<<nblkG, TB>>>(emb, x1, emb, 1);
    k_gather<false, false><<<nblkG, TB>>>(x1, x2, nullptr, 2);
    k_gather<false, true ><<<nblkG, TB>>>(x2, x1, nullptr, 3);

    // per-edge dot over edge_label_index
    long long dot_threads = (long long)E_EDGES * 16;
    k_dot<<<(int)((dot_threads + TB - 1) / TB), TB>>>(edge_label, res);
}

// round 7
// speedup vs baseline: 1.0872x; 1.0872x over previous
#include <cuda_runtime.h>
#include <cuda_bf16.h>

#define N_NODES 100000
#define E_EDGES 1250000
#define DIM     64
#define NL      3
#define SCAN_B  256
#define SCAN_NBLK ((N_NODES + SCAN_B - 1) / SCAN_B)   // 391

// ---- scratch (no allocations allowed) ----
__device__ float g_w[NL + 1];
__device__ int   g_cnt[N_NODES];
__device__ int   g_cur[N_NODES];
__device__ int   g_excl[N_NODES];
__device__ int   g_bsum[512];
__device__ int   g_boff[512];
__device__ int   g_rowptr[N_NODES + 1];
__device__ int   g_csrc[E_EDGES];
__device__ float g_cw[E_EDGES];
__device__ float g_dis[N_NODES];
__device__ float g_x1[N_NODES * DIM];
__device__ float g_x2[N_NODES * DIM];
__device__ float g_out[N_NODES * DIM];

// zero histogram; block 0 thread 0 also does the 4-way softmax
__global__ void k_prep(const float* __restrict__ alpha) {
    int i = blockIdx.x * blockDim.x + threadIdx.x;
    if (i < N_NODES) g_cnt[i] = 0;
    if (i == 0) {
        float m = alpha[0];
        for (int j = 1; j <= NL; j++) m = fmaxf(m, alpha[j]);
        float s = 0.f, e[NL + 1];
        for (int j = 0; j <= NL; j++) { e[j] = __expf(alpha[j] - m); s += e[j]; }
        for (int j = 0; j <= NL; j++) g_w[j] = e[j] / s;
    }
}

__global__ void k_count(const int* __restrict__ edge_index) {
    int e = blockIdx.x * blockDim.x + threadIdx.x;
    if (e < E_EDGES) atomicAdd(&g_cnt[edge_index[E_EDGES + e]], 1);
}

// per-block scan + block sums; also dis = rsqrt(deg) and g_cur zeroing (fused)
__global__ void k_scan1() {
    __shared__ int sh[SCAN_B];
    int t = threadIdx.x, b = blockIdx.x, i = b * SCAN_B + t;
    int v = (i < N_NODES) ? g_cnt[i] : 0;
    if (i < N_NODES) {
        g_dis[i] = (v > 0) ? rsqrtf((float)v) : 0.f;
        g_cur[i] = 0;
    }
    sh[t] = v; __syncthreads();
    #pragma unroll
    for (int off = 1; off < SCAN_B; off <<= 1) {
        int u = (t >= off) ? sh[t - off] : 0;
        __syncthreads();
        sh[t] += u;
        __syncthreads();
    }
    if (i < N_NODES) g_excl[i] = sh[t] - v;
    if (t == SCAN_B - 1) g_bsum[b] = sh[t];
}

// scan the 391 block sums in a single 512-thread block
__global__ void k_scan2() {
    __shared__ int sh[512];
    int t = threadIdx.x;
    int v = (t < SCAN_NBLK) ? g_bsum[t] : 0;
    sh[t] = v; __syncthreads();
    #pragma unroll
    for (int off = 1; off < 512; off <<= 1) {
        int u = (t >= off) ? sh[t - off] : 0;
        __syncthreads();
        sh[t] += u;
        __syncthreads();
    }
    if (t < SCAN_NBLK) g_boff[t] = sh[t] - v;
}

// combine: one boff load per block via shared broadcast
__global__ void k_scan3() {
    __shared__ int off;
    int i = blockIdx.x * blockDim.x + threadIdx.x;
    if (threadIdx.x == 0) off = g_boff[blockIdx.x];   // blockDim == SCAN_B
    __syncthreads();
    if (i < N_NODES) g_rowptr[i] = g_excl[i] + off;
    if (i == 0) g_rowptr[N_NODES] = E_EDGES;
}

// fill CSR: edge e -> slot in dst's range; weight = dis[src]*dis[dst]
__global__ void k_fill(const int* __restrict__ edge_index) {
    int e = blockIdx.x * blockDim.x + threadIdx.x;
    if (e < E_EDGES) {
        int s = edge_index[e];
        int t = edge_index[E_EDGES + e];
        int pos = g_rowptr[t] + atomicAdd(&g_cur[t], 1);
        g_csrc[pos] = s;
        g_cw[pos]   = g_dis[s] * g_dis[t];
    }
}

// Gather propagation: one warp per dst node, float2 per lane (256B row).
// 4-way unroll -> 4 independent row gathers in flight per warp.
// Fused epilogue: xout = acc (unless LAST); out (+)= w[widx]*acc [+ w0*emb if FIRST].
template<bool FIRST, bool LAST>
__global__ void k_gather(const float* __restrict__ xin,
                         float* __restrict__ xout,
                         const float* __restrict__ emb,
                         int widx) {
    int t = threadIdx.x;
    int node = blockIdx.x * 8 + (t >> 5);
    int lane = t & 31;
    if (node >= N_NODES) return;
    int i0 = g_rowptr[node], i1 = g_rowptr[node + 1];
    float ax = 0.f, ay = 0.f;
    int i = i0;
    int lim = i1 - 3;
    for (; i < lim; i += 4) {
        int   s0 = __ldg(&g_csrc[i]);
        int   s1 = __ldg(&g_csrc[i + 1]);
        int   s2 = __ldg(&g_csrc[i + 2]);
        int   s3 = __ldg(&g_csrc[i + 3]);
        float w0 = __ldg(&g_cw[i]);
        float w1 = __ldg(&g_cw[i + 1]);
        float w2 = __ldg(&g_cw[i + 2]);
        float w3 = __ldg(&g_cw[i + 3]);
        float2 v0 = *reinterpret_cast<const float2*>(xin + (size_t)s0 * DIM + lane * 2);
        float2 v1 = *reinterpret_cast<const float2*>(xin + (size_t)s1 * DIM + lane * 2);
        float2 v2 = *reinterpret_cast<const float2*>(xin + (size_t)s2 * DIM + lane * 2);
        float2 v3 = *reinterpret_cast<const float2*>(xin + (size_t)s3 * DIM + lane * 2);
        ax = fmaf(w0, v0.x, ax); ay = fmaf(w0, v0.y, ay);
        ax = fmaf(w1, v1.x, ax); ay = fmaf(w1, v1.y, ay);
        ax = fmaf(w2, v2.x, ax); ay = fmaf(w2, v2.y, ay);
        ax = fmaf(w3, v3.x, ax); ay = fmaf(w3, v3.y, ay);
    }
    for (; i < i1; i++) {
        int   s = __ldg(&g_csrc[i]);
        float w = __ldg(&g_cw[i]);
        float2 v = *reinterpret_cast<const float2*>(xin + (size_t)s * DIM + lane * 2);
        ax = fmaf(w, v.x, ax);
        ay = fmaf(w, v.y, ay);
    }
    size_t o = (size_t)node * DIM + lane * 2;
    if (!LAST)
        *reinterpret_cast<float2*>(xout + o) = make_float2(ax, ay);
    float wl = g_w[widx];
    float2* po = reinterpret_cast<float2*>(g_out + o);
    if (FIRST) {
        float2 e2 = *reinterpret_cast<const float2*>(emb + o);
        float w0 = g_w[0];
        *po = make_float2(fmaf(w0, e2.x, wl * ax), fmaf(w0, e2.y, wl * ay));
    } else {
        float2 c = *po;
        *po = make_float2(fmaf(wl, ax, c.x), fmaf(wl, ay, c.y));
    }
}

// dot: 16 lanes per edge, float4 per lane (256B coalesced row reads)
__global__ void k_dot(const int* __restrict__ eli, float* __restrict__ res) {
    int gt = blockIdx.x * blockDim.x + threadIdx.x;
    int e = gt >> 4, l = gt & 15;
    if (e >= E_EDGES) return;
    int a = __ldg(&eli[e]);
    int b = __ldg(&eli[E_EDGES + e]);
    float4 va = *reinterpret_cast<const float4*>(g_out + (size_t)a * DIM + l * 4);
    float4 vb = *reinterpret_cast<const float4*>(g_out + (size_t)b * DIM + l * 4);
    float s = va.x * vb.x + va.y * vb.y + va.z * vb.z + va.w * vb.w;
    #pragma unroll
    for (int off = 8; off > 0; off >>= 1)
        s += __shfl_xor_sync(0xffffffffu, s, off);
    if (l == 0) res[e] = s;
}

extern "C" void kernel_launch(void* const* d_in, const int* in_sizes, int n_in,
                              void* d_out, int out_size) {
    const int*   edge_index = (const int*)d_in[0];
    const int*   edge_label = (const int*)d_in[1];
    const float* emb        = (const float*)d_in[2];
    const float* alpha      = (const float*)d_in[3];
    float*       res        = (float*)d_out;

    float *x1, *x2;
    cudaGetSymbolAddress((void**)&x1, g_x1);
    cudaGetSymbolAddress((void**)&x2, g_x2);

    const int TB = 256;
    const int nblkN = (N_NODES + TB - 1) / TB;
    const int nblkE = (E_EDGES + TB - 1) / TB;
    const int nblkG = (N_NODES + 7) / 8;          // 8 nodes per 256-thread block

    // CSR build
    k_prep<<<nblkN, TB>>>(alpha);
    k_count<<<nblkE, TB>>>(edge_index);
    k_scan1<<<SCAN_NBLK, SCAN_B>>>();
    k_scan2<<<1, 512>>>();
    k_scan3<<<SCAN_NBLK, SCAN_B>>>();
    k_fill<<<nblkE, TB>>>(edge_index);

    // propagation (gather, no fp atomics), out-accum fused
    k_gather<true,  false><<<nblkG, TB>>>(emb, x1, emb, 1);
    k_gather<false, false><<<nblkG, TB>>>(x1, x2, nullptr, 2);
    k_gather<false, true ><<<nblkG, TB>>>(x2, x1, nullptr, 3);

    // per-edge dot over edge_label_index
    long long dot_threads = (long long)E_EDGES * 16;
    k_dot<<<(int)((dot_threads + TB - 1) / TB), TB>>>(edge_label, res);
}

// round 8
// speedup vs baseline: 1.0883x; 1.0010x over previous
#include <cuda_runtime.h>
#include <cuda_bf16.h>

#define N_NODES 100000
#define E_EDGES 1250000
#define DIM     64
#define NL      3
#define SCAN_B  256
#define SCAN_NBLK ((N_NODES + SCAN_B - 1) / SCAN_B)   // 391

// ---- scratch (no allocations allowed) ----
__device__ float g_w[NL + 1];
__device__ int   g_cnt[N_NODES];
__device__ int   g_cur[N_NODES];
__device__ int   g_excl[N_NODES];
__device__ int   g_bsum[512];
__device__ int   g_boff[512];
__device__ int   g_rowptr[N_NODES + 1];
__device__ int   g_csrc[E_EDGES];
__device__ float g_cw[E_EDGES];
__device__ float g_dis[N_NODES];
__device__ float g_x1[N_NODES * DIM];
__device__ float g_x2[N_NODES * DIM];
__device__ float g_out[N_NODES * DIM];

__global__ void k_count(const int* __restrict__ edge_index) {
    int e = blockIdx.x * blockDim.x + threadIdx.x;
    if (e < E_EDGES) atomicAdd(&g_cnt[edge_index[E_EDGES + e]], 1);
}

// per-block scan + block sums; also dis = rsqrt(deg) and g_cur zeroing (fused)
__global__ void k_scan1() {
    __shared__ int sh[SCAN_B];
    int t = threadIdx.x, b = blockIdx.x, i = b * SCAN_B + t;
    int v = (i < N_NODES) ? g_cnt[i] : 0;
    if (i < N_NODES) {
        g_dis[i] = (v > 0) ? rsqrtf((float)v) : 0.f;
        g_cur[i] = 0;
    }
    sh[t] = v; __syncthreads();
    #pragma unroll
    for (int off = 1; off < SCAN_B; off <<= 1) {
        int u = (t >= off) ? sh[t - off] : 0;
        __syncthreads();
        sh[t] += u;
        __syncthreads();
    }
    if (i < N_NODES) g_excl[i] = sh[t] - v;
    if (t == SCAN_B - 1) g_bsum[b] = sh[t];
}

// scan the 391 block sums in a single 512-thread block; thread 0 also does softmax
__global__ void k_scan2(const float* __restrict__ alpha) {
    __shared__ int sh[512];
    int t = threadIdx.x;
    if (t == 0) {
        float m = alpha[0];
        for (int j = 1; j <= NL; j++) m = fmaxf(m, alpha[j]);
        float s = 0.f, e[NL + 1];
        for (int j = 0; j <= NL; j++) { e[j] = __expf(alpha[j] - m); s += e[j]; }
        for (int j = 0; j <= NL; j++) g_w[j] = e[j] / s;
    }
    int v = (t < SCAN_NBLK) ? g_bsum[t] : 0;
    sh[t] = v; __syncthreads();
    #pragma unroll
    for (int off = 1; off < 512; off <<= 1) {
        int u = (t >= off) ? sh[t - off] : 0;
        __syncthreads();
        sh[t] += u;
        __syncthreads();
    }
    if (t < SCAN_NBLK) g_boff[t] = sh[t] - v;
}

// combine: one boff load per block via shared broadcast
__global__ void k_scan3() {
    __shared__ int off;
    int i = blockIdx.x * blockDim.x + threadIdx.x;
    if (threadIdx.x == 0) off = g_boff[blockIdx.x];   // blockDim == SCAN_B
    __syncthreads();
    if (i < N_NODES) g_rowptr[i] = g_excl[i] + off;
    if (i == 0) g_rowptr[N_NODES] = E_EDGES;
}

// fill CSR: edge e -> slot in dst's range; weight = dis[src]*dis[dst]
__global__ void k_fill(const int* __restrict__ edge_index) {
    int e = blockIdx.x * blockDim.x + threadIdx.x;
    if (e < E_EDGES) {
        int s = edge_index[e];
        int t = edge_index[E_EDGES + e];
        int pos = g_rowptr[t] + atomicAdd(&g_cur[t], 1);
        g_csrc[pos] = s;
        g_cw[pos]   = g_dis[s] * g_dis[t];
    }
}

// Gather propagation: one warp per dst node, float2 per lane (256B row).
// 4-way unroll -> 4 independent row gathers in flight per warp.
// Fused epilogue: xout = acc (unless LAST); out (+)= w[widx]*acc [+ w0*emb if FIRST].
template<bool FIRST, bool LAST>
__global__ void k_gather(const float* __restrict__ xin,
                         float* __restrict__ xout,
                         const float* __restrict__ emb,
                         int widx) {
    int t = threadIdx.x;
    int node = blockIdx.x * 8 + (t >> 5);
    int lane = t & 31;
    if (node >= N_NODES) return;
    int i0 = g_rowptr[node], i1 = g_rowptr[node + 1];
    float ax = 0.f, ay = 0.f;
    int i = i0;
    int lim = i1 - 3;
    for (; i < lim; i += 4) {
        int   s0 = __ldg(&g_csrc[i]);
        int   s1 = __ldg(&g_csrc[i + 1]);
        int   s2 = __ldg(&g_csrc[i + 2]);
        int   s3 = __ldg(&g_csrc[i + 3]);
        float w0 = __ldg(&g_cw[i]);
        float w1 = __ldg(&g_cw[i + 1]);
        float w2 = __ldg(&g_cw[i + 2]);
        float w3 = __ldg(&g_cw[i + 3]);
        float2 v0 = *reinterpret_cast<const float2*>(xin + (size_t)s0 * DIM + lane * 2);
        float2 v1 = *reinterpret_cast<const float2*>(xin + (size_t)s1 * DIM + lane * 2);
        float2 v2 = *reinterpret_cast<const float2*>(xin + (size_t)s2 * DIM + lane * 2);
        float2 v3 = *reinterpret_cast<const float2*>(xin + (size_t)s3 * DIM + lane * 2);
        ax = fmaf(w0, v0.x, ax); ay = fmaf(w0, v0.y, ay);
        ax = fmaf(w1, v1.x, ax); ay = fmaf(w1, v1.y, ay);
        ax = fmaf(w2, v2.x, ax); ay = fmaf(w2, v2.y, ay);
        ax = fmaf(w3, v3.x, ax); ay = fmaf(w3, v3.y, ay);
    }
    for (; i < i1; i++) {
        int   s = __ldg(&g_csrc[i]);
        float w = __ldg(&g_cw[i]);
        float2 v = *reinterpret_cast<const float2*>(xin + (size_t)s * DIM + lane * 2);
        ax = fmaf(w, v.x, ax);
        ay = fmaf(w, v.y, ay);
    }
    size_t o = (size_t)node * DIM + lane * 2;
    if (!LAST)
        *reinterpret_cast<float2*>(xout + o) = make_float2(ax, ay);
    float wl = g_w[widx];
    float2* po = reinterpret_cast<float2*>(g_out + o);
    if (FIRST) {
        float2 e2 = *reinterpret_cast<const float2*>(emb + o);
        float w0 = g_w[0];
        *po = make_float2(fmaf(w0, e2.x, wl * ax), fmaf(w0, e2.y, wl * ay));
    } else {
        float2 c = *po;
        *po = make_float2(fmaf(wl, ax, c.x), fmaf(wl, ay, c.y));
    }
}

// dot: 16 lanes per edge, float4 per lane (256B coalesced row reads)
__global__ void k_dot(const int* __restrict__ eli, float* __restrict__ res) {
    int gt = blockIdx.x * blockDim.x + threadIdx.x;
    int e = gt >> 4, l = gt & 15;
    if (e >= E_EDGES) return;
    int a = __ldg(&eli[e]);
    int b = __ldg(&eli[E_EDGES + e]);
    float4 va = *reinterpret_cast<const float4*>(g_out + (size_t)a * DIM + l * 4);
    float4 vb = *reinterpret_cast<const float4*>(g_out + (size_t)b * DIM + l * 4);
    float s = va.x * vb.x + va.y * vb.y + va.z * vb.z + va.w * vb.w;
    #pragma unroll
    for (int off = 8; off > 0; off >>= 1)
        s += __shfl_xor_sync(0xffffffffu, s, off);
    if (l == 0) res[e] = s;
}

extern "C" void kernel_launch(void* const* d_in, const int* in_sizes, int n_in,
                              void* d_out, int out_size) {
    const int*   edge_index = (const int*)d_in[0];
    const int*   edge_label = (const int*)d_in[1];
    const float* emb        = (const float*)d_in[2];
    const float* alpha      = (const float*)d_in[3];
    float*       res        = (float*)d_out;

    float *x1, *x2;
    int   *cntp;
    cudaGetSymbolAddress((void**)&x1,   g_x1);
    cudaGetSymbolAddress((void**)&x2,   g_x2);
    cudaGetSymbolAddress((void**)&cntp, g_cnt);

    const int TB = 256;
    const int nblkE = (E_EDGES + TB - 1) / TB;
    const int nblkG = (N_NODES + 7) / 8;          // 8 nodes per 256-thread block

    // CSR build (histogram zeroed by async memset — not a kernel launch)
    cudaMemsetAsync(cntp, 0, N_NODES * sizeof(int));
    k_count<<<nblkE, TB>>>(edge_index);           // launch 0
    k_scan1<<<SCAN_NBLK, SCAN_B>>>();             // launch 1
    k_scan2<<<1, 512>>>(alpha);                   // launch 2
    k_scan3<<<SCAN_NBLK, SCAN_B>>>();             // launch 3
    k_fill<<<nblkE, TB>>>(edge_index);            // launch 4

    // propagation (gather, no fp atomics), out-accum fused
    k_gather<true,  false><<<nblkG, TB>>>(emb, x1, emb, 1);   // launch 5 <- ncu -s 5
    k_gather<false, false><<<nblkG, TB>>>(x1, x2, nullptr, 2);
    k_gather<false, true ><<<nblkG, TB>>>(x2, x1, nullptr, 3);

    // per-edge dot over edge_label_index
    long long dot_threads = (long long)E_EDGES * 16;
    k_dot<<<(int)((dot_threads + TB - 1) / TB), TB>>>(edge_label, res);
}

// round 9
// speedup vs baseline: 1.0884x; 1.0001x over previous
#include <cuda_runtime.h>
#include <cuda_bf16.h>

#define N_NODES 100000
#define E_EDGES 1250000
#define DIM     64
#define NL      3
#define SCAN_B  256
#define SCAN_NBLK ((N_NODES + SCAN_B - 1) / SCAN_B)   // 391

// ---- scratch (no allocations allowed) ----
__device__ float g_w[NL + 1];
__device__ int   g_cnt[N_NODES];
__device__ int   g_cur[N_NODES];
__device__ int   g_excl[N_NODES];
__device__ int   g_bsum[512];
__device__ int   g_boff[512];
__device__ int   g_csrc[E_EDGES];
__device__ float g_cw[E_EDGES];
__device__ float g_dis[N_NODES];
__device__ float g_x1[N_NODES * DIM];
__device__ float g_x2[N_NODES * DIM];
__device__ float g_out[N_NODES * DIM];

__global__ void k_count(const int* __restrict__ edge_index) {
    int e = blockIdx.x * blockDim.x + threadIdx.x;
    if (e < E_EDGES) atomicAdd(&g_cnt[edge_index[E_EDGES + e]], 1);
}

// per-block scan + block sums; also dis = rsqrt(deg) and g_cur zeroing (fused)
__global__ void k_scan1() {
    __shared__ int sh[SCAN_B];
    int t = threadIdx.x, b = blockIdx.x, i = b * SCAN_B + t;
    int v = (i < N_NODES) ? g_cnt[i] : 0;
    if (i < N_NODES) {
        g_dis[i] = (v > 0) ? rsqrtf((float)v) : 0.f;
        g_cur[i] = 0;
    }
    sh[t] = v; __syncthreads();
    #pragma unroll
    for (int off = 1; off < SCAN_B; off <<= 1) {
        int u = (t >= off) ? sh[t - off] : 0;
        __syncthreads();
        sh[t] += u;
        __syncthreads();
    }
    if (i < N_NODES) g_excl[i] = sh[t] - v;
    if (t == SCAN_B - 1) g_bsum[b] = sh[t];
}

// scan the 391 block sums in a single 512-thread block; thread 0 also does softmax
__global__ void k_scan2(const float* __restrict__ alpha) {
    __shared__ int sh[512];
    int t = threadIdx.x;
    if (t == 0) {
        float m = alpha[0];
        for (int j = 1; j <= NL; j++) m = fmaxf(m, alpha[j]);
        float s = 0.f, e[NL + 1];
        for (int j = 0; j <= NL; j++) { e[j] = __expf(alpha[j] - m); s += e[j]; }
        for (int j = 0; j <= NL; j++) g_w[j] = e[j] / s;
    }
    int v = (t < SCAN_NBLK) ? g_bsum[t] : 0;
    sh[t] = v; __syncthreads();
    #pragma unroll
    for (int off = 1; off < 512; off <<= 1) {
        int u = (t >= off) ? sh[t - off] : 0;
        __syncthreads();
        sh[t] += u;
        __syncthreads();
    }
    if (t < SCAN_NBLK) g_boff[t] = sh[t] - v;
}

// rowptr(i) computed on the fly by consumers: g_excl[i] + g_boff[i >> 8]
__device__ __forceinline__ int rowptr_at(int i) {
    return (i < N_NODES) ? (g_excl[i] + g_boff[i >> 8]) : E_EDGES;
}

// fill CSR: edge e -> slot in dst's range; weight = dis[src]*dis[dst]
__global__ void k_fill(const int* __restrict__ edge_index) {
    int e = blockIdx.x * blockDim.x + threadIdx.x;
    if (e < E_EDGES) {
        int s = edge_index[e];
        int t = edge_index[E_EDGES + e];
        int pos = g_excl[t] + __ldg(&g_boff[t >> 8]) + atomicAdd(&g_cur[t], 1);
        g_csrc[pos] = s;
        g_cw[pos]   = g_dis[s] * g_dis[t];
    }
}

// Gather propagation: one warp per dst node, float2 per lane (256B row).
// 4-way unroll -> 4 independent row gathers in flight per warp.
// Fused epilogue: xout = acc (unless LAST); out (+)= w[widx]*acc [+ w0*emb if FIRST].
template<bool FIRST, bool LAST>
__global__ void k_gather(const float* __restrict__ xin,
                         float* __restrict__ xout,
                         const float* __restrict__ emb,
                         int widx) {
    int t = threadIdx.x;
    int node = blockIdx.x * 8 + (t >> 5);
    int lane = t & 31;
    if (node >= N_NODES) return;
    int i0 = rowptr_at(node);
    int i1 = rowptr_at(node + 1);
    float ax = 0.f, ay = 0.f;
    int i = i0;
    int lim = i1 - 3;
    for (; i < lim; i += 4) {
        int   s0 = __ldg(&g_csrc[i]);
        int   s1 = __ldg(&g_csrc[i + 1]);
        int   s2 = __ldg(&g_csrc[i + 2]);
        int   s3 = __ldg(&g_csrc[i + 3]);
        float w0 = __ldg(&g_cw[i]);
        float w1 = __ldg(&g_cw[i + 1]);
        float w2 = __ldg(&g_cw[i + 2]);
        float w3 = __ldg(&g_cw[i + 3]);
        float2 v0 = *reinterpret_cast<const float2*>(xin + (size_t)s0 * DIM + lane * 2);
        float2 v1 = *reinterpret_cast<const float2*>(xin + (size_t)s1 * DIM + lane * 2);
        float2 v2 = *reinterpret_cast<const float2*>(xin + (size_t)s2 * DIM + lane * 2);
        float2 v3 = *reinterpret_cast<const float2*>(xin + (size_t)s3 * DIM + lane * 2);
        ax = fmaf(w0, v0.x, ax); ay = fmaf(w0, v0.y, ay);
        ax = fmaf(w1, v1.x, ax); ay = fmaf(w1, v1.y, ay);
        ax = fmaf(w2, v2.x, ax); ay = fmaf(w2, v2.y, ay);
        ax = fmaf(w3, v3.x, ax); ay = fmaf(w3, v3.y, ay);
    }
    for (; i < i1; i++) {
        int   s = __ldg(&g_csrc[i]);
        float w = __ldg(&g_cw[i]);
        float2 v = *reinterpret_cast<const float2*>(xin + (size_t)s * DIM + lane * 2);
        ax = fmaf(w, v.x, ax);
        ay = fmaf(w, v.y, ay);
    }
    size_t o = (size_t)node * DIM + lane * 2;
    if (!LAST)
        *reinterpret_cast<float2*>(xout + o) = make_float2(ax, ay);
    float wl = g_w[widx];
    float2* po = reinterpret_cast<float2*>(g_out + o);
    if (FIRST) {
        float2 e2 = *reinterpret_cast<const float2*>(emb + o);
        float w0 = g_w[0];
        *po = make_float2(fmaf(w0, e2.x, wl * ax), fmaf(w0, e2.y, wl * ay));
    } else {
        float2 c = *po;
        *po = make_float2(fmaf(wl, ax, c.x), fmaf(wl, ay, c.y));
    }
}

// dot: 16 lanes per edge, float4 per lane (256B coalesced row reads)
__global__ void k_dot(const int* __restrict__ eli, float* __restrict__ res) {
    int gt = blockIdx.x * blockDim.x + threadIdx.x;
    int e = gt >> 4, l = gt & 15;
    if (e >= E_EDGES) return;
    int a = __ldg(&eli[e]);
    int b = __ldg(&eli[E_EDGES + e]);
    float4 va = *reinterpret_cast<const float4*>(g_out + (size_t)a * DIM + l * 4);
    float4 vb = *reinterpret_cast<const float4*>(g_out + (size_t)b * DIM + l * 4);
    float s = va.x * vb.x + va.y * vb.y + va.z * vb.z + va.w * vb.w;
    #pragma unroll
    for (int off = 8; off > 0; off >>= 1)
        s += __shfl_xor_sync(0xffffffffu, s, off);
    if (l == 0) res[e] = s;
}

extern "C" void kernel_launch(void* const* d_in, const int* in_sizes, int n_in,
                              void* d_out, int out_size) {
    const int*   edge_index = (const int*)d_in[0];
    const int*   edge_label = (const int*)d_in[1];
    const float* emb        = (const float*)d_in[2];
    const float* alpha      = (const float*)d_in[3];
    float*       res        = (float*)d_out;

    float *x1, *x2;
    int   *cntp;
    cudaGetSymbolAddress((void**)&x1,   g_x1);
    cudaGetSymbolAddress((void**)&x2,   g_x2);
    cudaGetSymbolAddress((void**)&cntp, g_cnt);

    const int TB = 256;
    const int nblkE = (E_EDGES + TB - 1) / TB;
    const int nblkG = (N_NODES + 7) / 8;          // 8 nodes per 256-thread block

    // CSR build (histogram zeroed by async memset)
    cudaMemsetAsync(cntp, 0, N_NODES * sizeof(int));   // node 0
    k_count<<<nblkE, TB>>>(edge_index);                // node 1
    k_scan1<<<SCAN_NBLK, SCAN_B>>>();                  // node 2
    k_scan2<<<1, 512>>>(alpha);                        // node 3
    k_fill<<<nblkE, TB>>>(edge_index);                 // node 4

    // propagation (gather, no fp atomics), out-accum fused
    k_gather<true,  false><<<nblkG, TB>>>(emb, x1, emb, 1);   // node 5 <- ncu -s 5
    k_gather<false, false><<<nblkG, TB>>>(x1, x2, nullptr, 2);
    k_gather<false, true ><<<nblkG, TB>>>(x2, x1, nullptr, 3);

    // per-edge dot over edge_label_index
    long long dot_threads = (long long)E_EDGES * 16;
    k_dot<<<(int)((dot_threads + TB - 1) / TB), TB>>>(edge_label, res);
}

// round 10
// speedup vs baseline: 1.1080x; 1.0180x over previous
#include <cuda_runtime.h>
#include <cuda_bf16.h>

#define N_NODES 100000
#define E_EDGES 1250000
#define DIM     64
#define NL      3
#define SCAN_B  256
#define SCAN_NBLK ((N_NODES + SCAN_B - 1) / SCAN_B)   // 391

// ---- scratch (no allocations allowed) ----
__device__ float g_w[NL + 1];
__device__ int   g_cnt[N_NODES];
__device__ int   g_rank[E_EDGES];
__device__ int   g_excl[N_NODES];
__device__ int   g_bsum[512];
__device__ int   g_boff[512];
__device__ int   g_csrc[E_EDGES];
__device__ float g_cw[E_EDGES];
__device__ float g_dis[N_NODES];
__device__ float g_x1[N_NODES * DIM];
__device__ float g_x2[N_NODES * DIM];
__device__ float g_out[N_NODES * DIM];

// histogram; atomic return value = unique within-row rank
__global__ void k_count(const int* __restrict__ edge_index) {
    int e = blockIdx.x * blockDim.x + threadIdx.x;
    if (e < E_EDGES)
        g_rank[e] = atomicAdd(&g_cnt[edge_index[E_EDGES + e]], 1);
}

// per-block scan + block sums; also dis = rsqrt(deg) (fused)
__global__ void k_scan1() {
    __shared__ int sh[SCAN_B];
    int t = threadIdx.x, b = blockIdx.x, i = b * SCAN_B + t;
    int v = (i < N_NODES) ? g_cnt[i] : 0;
    if (i < N_NODES)
        g_dis[i] = (v > 0) ? rsqrtf((float)v) : 0.f;
    sh[t] = v; __syncthreads();
    #pragma unroll
    for (int off = 1; off < SCAN_B; off <<= 1) {
        int u = (t >= off) ? sh[t - off] : 0;
        __syncthreads();
        sh[t] += u;
        __syncthreads();
    }
    if (i < N_NODES) g_excl[i] = sh[t] - v;
    if (t == SCAN_B - 1) g_bsum[b] = sh[t];
}

// scan the 391 block sums in a single 512-thread block; thread 0 also does softmax
__global__ void k_scan2(const float* __restrict__ alpha) {
    __shared__ int sh[512];
    int t = threadIdx.x;
    if (t == 0) {
        float m = alpha[0];
        for (int j = 1; j <= NL; j++) m = fmaxf(m, alpha[j]);
        float s = 0.f, e[NL + 1];
        for (int j = 0; j <= NL; j++) { e[j] = __expf(alpha[j] - m); s += e[j]; }
        for (int j = 0; j <= NL; j++) g_w[j] = e[j] / s;
    }
    int v = (t < SCAN_NBLK) ? g_bsum[t] : 0;
    sh[t] = v; __syncthreads();
    #pragma unroll
    for (int off = 1; off < 512; off <<= 1) {
        int u = (t >= off) ? sh[t - off] : 0;
        __syncthreads();
        sh[t] += u;
        __syncthreads();
    }
    if (t < SCAN_NBLK) g_boff[t] = sh[t] - v;
}

// rowptr(i) computed on the fly by consumers: g_excl[i] + g_boff[i >> 8]
__device__ __forceinline__ int rowptr_at(int i) {
    return (i < N_NODES) ? (g_excl[i] + g_boff[i >> 8]) : E_EDGES;
}

// fill CSR: no atomics (rank precomputed); payload = src index + dis[src].
// dis[dst] factor applied in gather epilogue (row-uniform).
__global__ void k_fill(const int* __restrict__ edge_index) {
    int e = blockIdx.x * blockDim.x + threadIdx.x;
    if (e < E_EDGES) {
        int s = edge_index[e];
        int t = edge_index[E_EDGES + e];
        int pos = g_excl[t] + __ldg(&g_boff[t >> 8]) + g_rank[e];
        g_csrc[pos] = s;
        g_cw[pos]   = g_dis[s];
    }
}

// Gather propagation: one warp per dst node, float2 per lane (256B row).
// acc = dis[dst] * sum_e dis[src_e] * x[src_e]
// Fused epilogue: xout = acc (unless LAST); out (+)= w[widx]*acc [+ w0*emb if FIRST].
template<bool FIRST, bool LAST>
__global__ void k_gather(const float* __restrict__ xin,
                         float* __restrict__ xout,
                         const float* __restrict__ emb,
                         int widx) {
    int t = threadIdx.x;
    int node = blockIdx.x * 8 + (t >> 5);
    int lane = t & 31;
    if (node >= N_NODES) return;
    int i0 = rowptr_at(node);
    int i1 = rowptr_at(node + 1);
    float ax = 0.f, ay = 0.f;
    int i = i0;
    int lim = i1 - 3;
    for (; i < lim; i += 4) {
        int   s0 = __ldg(&g_csrc[i]);
        int   s1 = __ldg(&g_csrc[i + 1]);
        int   s2 = __ldg(&g_csrc[i + 2]);
        int   s3 = __ldg(&g_csrc[i + 3]);
        float w0 = __ldg(&g_cw[i]);
        float w1 = __ldg(&g_cw[i + 1]);
        float w2 = __ldg(&g_cw[i + 2]);
        float w3 = __ldg(&g_cw[i + 3]);
        float2 v0 = *reinterpret_cast<const float2*>(xin + (size_t)s0 * DIM + lane * 2);
        float2 v1 = *reinterpret_cast<const float2*>(xin + (size_t)s1 * DIM + lane * 2);
        float2 v2 = *reinterpret_cast<const float2*>(xin + (size_t)s2 * DIM + lane * 2);
        float2 v3 = *reinterpret_cast<const float2*>(xin + (size_t)s3 * DIM + lane * 2);
        ax = fmaf(w0, v0.x, ax); ay = fmaf(w0, v0.y, ay);
        ax = fmaf(w1, v1.x, ax); ay = fmaf(w1, v1.y, ay);
        ax = fmaf(w2, v2.x, ax); ay = fmaf(w2, v2.y, ay);
        ax = fmaf(w3, v3.x, ax); ay = fmaf(w3, v3.y, ay);
    }
    for (; i < i1; i++) {
        int   s = __ldg(&g_csrc[i]);
        float w = __ldg(&g_cw[i]);
        float2 v = *reinterpret_cast<const float2*>(xin + (size_t)s * DIM + lane * 2);
        ax = fmaf(w, v.x, ax);
        ay = fmaf(w, v.y, ay);
    }
    float disd = g_dis[node];
    ax *= disd; ay *= disd;
    size_t o = (size_t)node * DIM + lane * 2;
    if (!LAST)
        *reinterpret_cast<float2*>(xout + o) = make_float2(ax, ay);
    float wl = g_w[widx];
    float2* po = reinterpret_cast<float2*>(g_out + o);
    if (FIRST) {
        float2 e2 = *reinterpret_cast<const float2*>(emb + o);
        float w0 = g_w[0];
        *po = make_float2(fmaf(w0, e2.x, wl * ax), fmaf(w0, e2.y, wl * ay));
    } else {
        float2 c = *po;
        *po = make_float2(fmaf(wl, ax, c.x), fmaf(wl, ay, c.y));
    }
}

// dot: 16 lanes per edge, float4 per lane (256B coalesced row reads)
__global__ void k_dot(const int* __restrict__ eli, float* __restrict__ res) {
    int gt = blockIdx.x * blockDim.x + threadIdx.x;
    int e = gt >> 4, l = gt & 15;
    if (e >= E_EDGES) return;
    int a = __ldg(&eli[e]);
    int b = __ldg(&eli[E_EDGES + e]);
    float4 va = *reinterpret_cast<const float4*>(g_out + (size_t)a * DIM + l * 4);
    float4 vb = *reinterpret_cast<const float4*>(g_out + (size_t)b * DIM + l * 4);
    float s = va.x * vb.x + va.y * vb.y + va.z * vb.z + va.w * vb.w;
    #pragma unroll
    for (int off = 8; off > 0; off >>= 1)
        s += __shfl_xor_sync(0xffffffffu, s, off);
    if (l == 0) res[e] = s;
}

extern "C" void kernel_launch(void* const* d_in, const int* in_sizes, int n_in,
                              void* d_out, int out_size) {
    const int*   edge_index = (const int*)d_in[0];
    const int*   edge_label = (const int*)d_in[1];
    const float* emb        = (const float*)d_in[2];
    const float* alpha      = (const float*)d_in[3];
    float*       res        = (float*)d_out;

    float *x1, *x2;
    int   *cntp;
    cudaGetSymbolAddress((void**)&x1,   g_x1);
    cudaGetSymbolAddress((void**)&x2,   g_x2);
    cudaGetSymbolAddress((void**)&cntp, g_cnt);

    const int TB = 256;
    const int nblkE = (E_EDGES + TB - 1) / TB;
    const int nblkG = (N_NODES + 7) / 8;          // 8 nodes per 256-thread block

    // CSR build (histogram zeroed by async memset)
    cudaMemsetAsync(cntp, 0, N_NODES * sizeof(int));
    k_count<<<nblkE, TB>>>(edge_index);
    k_scan1<<<SCAN_NBLK, SCAN_B>>>();
    k_scan2<<<1, 512>>>(alpha);
    k_fill<<<nblkE, TB>>>(edge_index);

    // propagation (gather, no fp atomics), out-accum fused
    k_gather<true,  false><<<nblkG, TB>>>(emb, x1, emb, 1);
    k_gather<false, false><<<nblkG, TB>>>(x1, x2, nullptr, 2);
    k_gather<false, true ><<<nblkG, TB>>>(x2, x1, nullptr, 3);

    // per-edge dot over edge_label_index
    long long dot_threads = (long long)E_EDGES * 16;
    k_dot<<<(int)((dot_threads + TB - 1) / TB), TB>>>(edge_label, res);
}